// round 7
// baseline (speedup 1.0000x reference)
#include <cuda_runtime.h>
#include <cstdint>

// Geometry fixed by dataset: 2 inputs of (8,1,1024,1024) fp32.
#define HH 1024
#define WW 1024
#define NB 8
#define PLANE (HH*WW)

static __device__ double g_acc;

// ---------------------------------------------------------------------------
// Gaussian weights as compile-time immediates
// ---------------------------------------------------------------------------
#define E05f 0.6065306597126334f     /* exp(-0.5) */
#define E20f 0.1353352832366127f     /* exp(-2)   */
#define E45f 0.011108996538242306f   /* exp(-4.5) */
#define E80f 0.00033546262790251185f /* exp(-8)   */

constexpr float G7S = 1.f + 2.f*(E05f + E20f + E45f);
constexpr float G70 = E45f/G7S, G71 = E20f/G7S, G72 = E05f/G7S, G73 = 1.f/G7S;
constexpr float G5S = 1.f + 2.f*(E20f + E80f);
constexpr float G50 = E80f/G5S, G51 = E20f/G5S, G52 = 1.f/G5S;

// ---------------------------------------------------------------------------
// Sobel helpers (cross-correlation, XLA conv semantics)
// SOBEL_X = [[-1,0,1],[-2,0,2],[-1,0,1]]  SOBEL_Y = [[1,2,1],[0,0,0],[-1,-2,-1]]
// ---------------------------------------------------------------------------
__device__ __forceinline__ float sobx(const float* s, int st, int i, int j) {
    const float* a = s + (i-1)*st + j;
    const float* b = s + (i  )*st + j;
    const float* c = s + (i+1)*st + j;
    return (a[1]-a[-1]) + 2.f*(b[1]-b[-1]) + (c[1]-c[-1]);
}
__device__ __forceinline__ float soby(const float* s, int st, int i, int j) {
    const float* a = s + (i-1)*st + j;
    const float* c = s + (i+1)*st + j;
    return (a[-1]+2.f*a[0]+a[1]) - (c[-1]+2.f*c[0]+c[1]);
}

// ---------------------------------------------------------------------------
// Shared-memory pool layout (floats), manually aliased by phase:
//   raw [48x48 @48]  : persistent (also the I tile for div)     @ 0
//   S   [36x36 @38]  : persistent per t                          @ 2304
//   gJ  [36x36 @38]  : persistent per t                          @ 3672
//   scratch region                                               @ 5040..9800
//     phase hb : hb  [48x42 @44] @5040 ; isg [42x42 @44] @7152
//     phase sq : sq  [40x40 @42] @5040 (aliases hb) ; isg alive
//     phase h5 : h5  [40x36 @38] @7152 (aliases isg); sq alive
//     phase fx : fxI/fyI/fxJ/fyJ [34x34 @35] @5040 +1190 each
// Total 9800 floats = 39200 B.
// ---------------------------------------------------------------------------
#define PO_RAW  0
#define PO_S    2304
#define PO_GJ   3672
#define PO_HB   5040
#define PO_ISG  7152
#define PO_SQ   5040
#define PO_H5   7152
#define PO_FXI  5040
#define PO_FYI  6230
#define PO_FXJ  7420
#define PO_FYJ  8610
#define PO_TOT  9800

// ---------------------------------------------------------------------------
// k_all: the ENTIRE pipeline per 32x32 output tile, for pred and target,
// accumulating (dI_p-dI_t)^2 + (dJ_p-dJ_t)^2 directly.  No scratch GMEM.
// raw halo 8 (48x48).  block (32,32), grid (32,32,8).
// Zero-padding semantics: raw, isg, sq, flux are ZERO outside the image.
// ---------------------------------------------------------------------------
__global__ __launch_bounds__(1024) void k_all(const float* __restrict__ Ip,
                                              const float* __restrict__ It) {
    __shared__ float pool[PO_TOT];
    __shared__ float wsum[32];
    float* const raw = pool + PO_RAW;
    float* const S   = pool + PO_S;
    float* const gJ  = pool + PO_GJ;
    float* const hb  = pool + PO_HB;
    float* const isg = pool + PO_ISG;
    float* const sq  = pool + PO_SQ;
    float* const h5  = pool + PO_H5;
    float* const fxI = pool + PO_FXI;
    float* const fyI = pool + PO_FYI;
    float* const fxJ = pool + PO_FXJ;
    float* const fyJ = pool + PO_FYJ;

    const int z  = blockIdx.z;
    const int r0 = blockIdx.y*32, c0 = blockIdx.x*32;
    const int ty = threadIdx.y, tx = threadIdx.x;
    const int tid = ty*32 + tx;
    const bool interior = (blockIdx.x >= 1 && blockIdx.x <= 30 &&
                           blockIdx.y >= 1 && blockIdx.y <= 30);

    float dI_[2], dJ_[2];

    for (int t = 0; t < 2; ++t) {
        const float* img = (t ? It : Ip) + (size_t)z*PLANE;

        // ---- raw: 48x48 at (r0-8, c0-8); zero outside image ----
        if (interior) {
            const float4* base = (const float4*)(img + (r0-8)*WW + (c0-8));
            for (int idx = tid; idx < 48*12; idx += 1024) {
                int i = idx / 12, j = idx - i*12;
                ((float4*)raw)[i*12 + j] = base[i*(WW/4) + j];
            }
        } else {
            for (int idx = tid; idx < 48*48; idx += 1024) {
                int i = idx / 48, j = idx - i*48;
                int gr = r0-8+i, gc = c0-8+j;
                raw[idx] = ((unsigned)gr < HH && (unsigned)gc < WW) ? img[gr*WW+gc] : 0.f;
            }
        }
        __syncthreads();

        // ---- hb: h-gauss7, 48 rows x 42 cols; hb(i,j) at col c0-5+j ----
        for (int idx = tid; idx < 48*42; idx += 1024) {
            int i = idx / 42, j = idx - i*42;
            const float* r = raw + i*48 + j;
            hb[i*44+j] = G70*(r[0]+r[6]) + G71*(r[1]+r[5]) + G72*(r[2]+r[4]) + G73*r[3];
        }
        __syncthreads();

        // ---- isg: v-gauss7, 42x42 at (r0-5, c0-5); ZERO outside image ----
        for (int idx = tid; idx < 42*42; idx += 1024) {
            int i = idx / 42, j = idx - i*42;
            float v = 0.f;
            if (interior || ((unsigned)(r0-5+i) < HH && (unsigned)(c0-5+j) < WW)) {
                const float* h = hb + i*44 + j;
                v = G70*(h[0]+h[6*44]) + G71*(h[44]+h[5*44])
                  + G72*(h[2*44]+h[4*44]) + G73*h[3*44];
            }
            isg[i*44+j] = v;
        }
        __syncthreads();

        // ---- sq: |sobel(isg)|^2, 40x40 at (r0-4, c0-4); ZERO outside ----
        // (sq aliases hb; isg still alive)
        for (int idx = tid; idx < 40*40; idx += 1024) {
            int i = idx / 40, j = idx - i*40;
            float v = 0.f;
            if (interior || ((unsigned)(r0-4+i) < HH && (unsigned)(c0-4+j) < WW)) {
                float sx = sobx(isg, 44, i+1, j+1);
                float sy = soby(isg, 44, i+1, j+1);
                v = sx*sx + sy*sy;
            }
            sq[i*42+j] = v;
        }
        __syncthreads();

        // ---- h5: h-gauss5 of sq, 40 rows x 36 cols; h5(i,j) at col c0-2+j ----
        // (h5 aliases isg; sq alive)
        for (int idx = tid; idx < 40*36; idx += 1024) {
            int i = idx / 36, j = idx - i*36;
            const float* p = sq + i*42 + j;
            h5[i*38+j] = G50*(p[0]+p[4]) + G51*(p[1]+p[3]) + G52*p[2];
        }
        __syncthreads();

        // ---- S = v-gauss5(h5), gJ = edge-stop; 36x36 at (r0-2, c0-2) ----
        for (int idx = tid; idx < 36*36; idx += 1024) {
            int i = idx / 36, j = idx - i*36;
            const float* p = h5 + i*38 + j;
            S[i*38+j]  = G50*(p[0]+p[4*38]) + G51*(p[38]+p[3*38]) + G52*p[2*38];
            // edge_stop(sqrt(v+1e-6)) with P=2,K=20 == 1/(1 + (v+1e-6)/400)
            float gn2 = sq[(i+2)*42 + (j+2)] + 1e-6f;
            gJ[i*38+j] = 1.f/(1.f + gn2*(1.f/400.f));
        }
        __syncthreads();

        // ---- flux: 34x34 at (r0-1, c0-1); ZERO outside image ----
        // (flux aliases the whole scratch region; sq/h5 dead)
        for (int idx = tid; idx < 34*34; idx += 1024) {
            int i = idx / 34, j = idx - i*34;
            bool in = interior ||
                      ((unsigned)(r0-1+i) < HH && (unsigned)(c0-1+j) < WW);
            float gI = 0.f, g = 0.f;
            if (in) {
                int ci = (i+1)*38 + (j+1);
                gI = 1.f/(1.f + (S[ci] + 1e-6f)*(1.f/400.f));
                g  = gJ[ci];
            }
            int fo = i*35 + j;
            fxI[fo] = gI*sobx(raw, 48, i+7, j+7);
            fyI[fo] = gI*soby(raw, 48, i+7, j+7);
            fxJ[fo] = g *sobx(S,   38, i+1, j+1);
            fyJ[fo] = g *soby(S,   38, i+1, j+1);
        }
        __syncthreads();

        // ---- combine: one output pixel per thread ----
        dI_[t] = sobx(fxI, 35, ty+1, tx+1) + soby(fyI, 35, ty+1, tx+1);
        dJ_[t] = sobx(fxJ, 35, ty+1, tx+1) + soby(fyJ, 35, ty+1, tx+1);
        __syncthreads();   // protect pool before next t / reduction
    }

    float ddi = dI_[0] - dI_[1], ddj = dJ_[0] - dJ_[1];
    float s = ddi*ddi + ddj*ddj;

    // warp-shuffle reduction
    #pragma unroll
    for (int o = 16; o > 0; o >>= 1) s += __shfl_down_sync(0xffffffffu, s, o);
    if ((tid & 31) == 0) wsum[tid >> 5] = s;
    __syncthreads();
    if (tid < 32) {
        float v = wsum[tid];
        #pragma unroll
        for (int o = 16; o > 0; o >>= 1) v += __shfl_down_sync(0xffffffffu, v, o);
        if (tid == 0) atomicAdd(&g_acc, (double)v);
    }
}

// ---------------------------------------------------------------------------
__global__ void k_zero() { g_acc = 0.0; }
__global__ void k_fin(float* __restrict__ out) {
    out[0] = (float)(g_acc * (1.0/8388608.0));   // /(8*1024*1024)
}

// ---------------------------------------------------------------------------
extern "C" void kernel_launch(void* const* d_in, const int* in_sizes, int n_in,
                              void* d_out, int out_size) {
    (void)in_sizes; (void)n_in; (void)out_size;
    const float* pred = (const float*)d_in[0];
    const float* targ = (const float*)d_in[1];
    float* out = (float*)d_out;

    k_zero<<<1, 1>>>();
    k_all<<<dim3(WW/32, HH/32, NB), dim3(32, 32)>>>(pred, targ);
    k_fin<<<1, 1>>>(out);
}